// round 1
// baseline (speedup 1.0000x reference)
#include <cuda_runtime.h>
#include <math.h>

#define SEQ 4096
#define DM  768
#define NH  12
#define HD  64
#define BQ  64
#define BK  64

// Scratch (allocation-free rule: __device__ globals)
__device__ float g_Q[SEQ * DM];
__device__ float g_K[SEQ * DM];
__device__ float g_V[SEQ * DM];
__device__ float g_AO[SEQ * DM];

// ---------------------------------------------------------------------------
// GEMM: C[M,N] = A[M,K] @ B[N,K]^T (+ bias[N])
// Block 64x64, Ktile 16, 256 threads, 4x4 micro-tile.
// ---------------------------------------------------------------------------
template <bool HAS_BIAS>
__global__ __launch_bounds__(256) void gemm_nt(
    const float* __restrict__ A, const float* __restrict__ B,
    const float* __restrict__ bias, float* __restrict__ C,
    int M, int N, int K)
{
    __shared__ float As[16][64];   // [k][m]
    __shared__ float Bs[16][64];   // [k][n]

    const int m0 = blockIdx.y * 64;
    const int n0 = blockIdx.x * 64;
    const int t  = threadIdx.x;
    const int tx = t & 15;         // n quad
    const int ty = t >> 4;         // m quad
    const int lr = t >> 2;         // load row 0..63
    const int lc = (t & 3) << 2;   // load col 0,4,8,12

    float acc[4][4];
#pragma unroll
    for (int i = 0; i < 4; i++)
#pragma unroll
        for (int j = 0; j < 4; j++) acc[i][j] = 0.0f;

    const float* Ap = A + (size_t)(m0 + lr) * K + lc;
    const float* Bp = B + (size_t)(n0 + lr) * K + lc;

    for (int k0 = 0; k0 < K; k0 += 16) {
        float4 av = *(const float4*)(Ap + k0);
        float4 bv = *(const float4*)(Bp + k0);
        __syncthreads();
        As[lc + 0][lr] = av.x; As[lc + 1][lr] = av.y;
        As[lc + 2][lr] = av.z; As[lc + 3][lr] = av.w;
        Bs[lc + 0][lr] = bv.x; Bs[lc + 1][lr] = bv.y;
        Bs[lc + 2][lr] = bv.z; Bs[lc + 3][lr] = bv.w;
        __syncthreads();
#pragma unroll
        for (int k = 0; k < 16; k++) {
            float4 a = *(const float4*)&As[k][ty << 2];
            float4 b = *(const float4*)&Bs[k][tx << 2];
            acc[0][0] += a.x * b.x; acc[0][1] += a.x * b.y;
            acc[0][2] += a.x * b.z; acc[0][3] += a.x * b.w;
            acc[1][0] += a.y * b.x; acc[1][1] += a.y * b.y;
            acc[1][2] += a.y * b.z; acc[1][3] += a.y * b.w;
            acc[2][0] += a.z * b.x; acc[2][1] += a.z * b.y;
            acc[2][2] += a.z * b.z; acc[2][3] += a.z * b.w;
            acc[3][0] += a.w * b.x; acc[3][1] += a.w * b.y;
            acc[3][2] += a.w * b.z; acc[3][3] += a.w * b.w;
        }
    }

    const int col = n0 + (tx << 2);
    float4 bb = make_float4(0.f, 0.f, 0.f, 0.f);
    if (HAS_BIAS) bb = *(const float4*)&bias[col];
#pragma unroll
    for (int i = 0; i < 4; i++) {
        int row = m0 + (ty << 2) + i;
        float4 o = make_float4(acc[i][0] + bb.x, acc[i][1] + bb.y,
                               acc[i][2] + bb.z, acc[i][3] + bb.w);
        *(float4*)&C[(size_t)row * N + col] = o;
    }
}

// ---------------------------------------------------------------------------
// RoPE (in-place, split-halves output layout, matching the reference):
// out[d]    = x[2d]*cos - x[2d+1]*sin        (d in [0,32))
// out[d+32] = x[2d]*sin + x[2d+1]*cos
// One warp per (s, h); lane = pair index d.
// ---------------------------------------------------------------------------
__global__ __launch_bounds__(256) void rope_kernel(float* __restrict__ Q,
                                                   float* __restrict__ Kp)
{
    int gw   = (blockIdx.x * 256 + threadIdx.x) >> 5;
    int lane = threadIdx.x & 31;
    if (gw >= SEQ * NH) return;
    int s = gw / NH;
    int h = gw % NH;

    float inv_freq = (float)exp(-(double)(2 * lane) / (double)HD * log(10000.0));
    float ang = (float)s * inv_freq;
    float sn, c;
    sincosf(ang, &sn, &c);

    float* q = Q  + (size_t)s * DM + h * HD;
    float* k = Kp + (size_t)s * DM + h * HD;
    float2 qv = *(const float2*)(q + 2 * lane);
    float2 kv = *(const float2*)(k + 2 * lane);
    __syncwarp();
    q[lane]      = qv.x * c  - qv.y * sn;
    q[lane + 32] = qv.x * sn + qv.y * c;
    k[lane]      = kv.x * c  - kv.y * sn;
    k[lane + 32] = kv.x * sn + kv.y * c;
}

// ---------------------------------------------------------------------------
// Flash attention, fp32, causal. BQ=BK=64, 256 threads.
// Thread (ty,tx): rows ry..ry+3 (ry=4*ty), cols dx..dx+3 (dx=4*tx)
// for both the score tile and the output accumulator.
// ---------------------------------------------------------------------------
#define SMEM_FLOATS (3 * 64 * 65 + 64 * 64)
#define SMEM_BYTES  (SMEM_FLOATS * 4)

__global__ __launch_bounds__(256) void flash_attn(
    const float* __restrict__ Q, const float* __restrict__ K,
    const float* __restrict__ V, float* __restrict__ O)
{
    extern __shared__ float sm[];
    float* Qs  = sm;                 // [64][65]  Qs[r*65+d]
    float* Kst = sm + 64 * 65;       // [64][65]  Kst[d*65+kk]  (d-major!)
    float* Vs  = sm + 2 * 64 * 65;   // [64][65]  Vs[kk*65+d]
    float* Ps  = sm + 3 * 64 * 65;   // [64][64]  Ps[r*64+kk]

    const int h  = blockIdx.y;
    const int qb = gridDim.x - 1 - blockIdx.x;   // big causal rows first
    const int q0 = qb * BQ;
    const int t  = threadIdx.x;
    const int tx = t & 15;
    const int ty = t >> 4;
    const int ry = ty << 2;
    const int dx = tx << 2;

    // Load Q tile
    for (int i = t; i < BQ * HD / 4; i += 256) {
        int r = i >> 4;
        int c = (i & 15) << 2;
        float4 v = *(const float4*)&Q[(size_t)(q0 + r) * DM + h * HD + c];
        Qs[r * 65 + c + 0] = v.x; Qs[r * 65 + c + 1] = v.y;
        Qs[r * 65 + c + 2] = v.z; Qs[r * 65 + c + 3] = v.w;
    }

    float m_[4], l_[4], acc[4][4];
#pragma unroll
    for (int i = 0; i < 4; i++) {
        m_[i] = -1e30f; l_[i] = 0.0f;
#pragma unroll
        for (int j = 0; j < 4; j++) acc[i][j] = 0.0f;
    }

    for (int jb = 0; jb <= qb; jb++) {
        const int k0 = jb * BK;
        __syncthreads();   // previous tile fully consumed (also covers Q load)

        // Load K transposed (Kst[d][kk]) — coalesced global reads
        {
            int d  = t & 63;
            int kq = (t >> 6) << 4;  // 0,16,32,48
#pragma unroll
            for (int j = 0; j < 16; j++)
                Kst[d * 65 + kq + j] =
                    K[(size_t)(k0 + kq + j) * DM + h * HD + d];
        }
        // Load V tile
        for (int i = t; i < BK * HD / 4; i += 256) {
            int r = i >> 4;
            int c = (i & 15) << 2;
            float4 v = *(const float4*)&V[(size_t)(k0 + r) * DM + h * HD + c];
            Vs[r * 65 + c + 0] = v.x; Vs[r * 65 + c + 1] = v.y;
            Vs[r * 65 + c + 2] = v.z; Vs[r * 65 + c + 3] = v.w;
        }
        __syncthreads();

        // Scores: sc[i][j] = Q[ry+i] . K[k0+dx+j]
        float sc[4][4];
#pragma unroll
        for (int i = 0; i < 4; i++)
#pragma unroll
            for (int j = 0; j < 4; j++) sc[i][j] = 0.0f;

        for (int d = 0; d < HD; d++) {
            float a0 = Qs[(ry + 0) * 65 + d];
            float a1 = Qs[(ry + 1) * 65 + d];
            float a2 = Qs[(ry + 2) * 65 + d];
            float a3 = Qs[(ry + 3) * 65 + d];
            float b0 = Kst[d * 65 + dx + 0];
            float b1 = Kst[d * 65 + dx + 1];
            float b2 = Kst[d * 65 + dx + 2];
            float b3 = Kst[d * 65 + dx + 3];
            sc[0][0] += a0 * b0; sc[0][1] += a0 * b1; sc[0][2] += a0 * b2; sc[0][3] += a0 * b3;
            sc[1][0] += a1 * b0; sc[1][1] += a1 * b1; sc[1][2] += a1 * b2; sc[1][3] += a1 * b3;
            sc[2][0] += a2 * b0; sc[2][1] += a2 * b1; sc[2][2] += a2 * b2; sc[2][3] += a2 * b3;
            sc[3][0] += a3 * b0; sc[3][1] += a3 * b1; sc[3][2] += a3 * b2; sc[3][3] += a3 * b3;
        }

        // Scale + causal mask (reference uses exactly -1e9 sentinel)
        const bool diag = (jb == qb);
#pragma unroll
        for (int i = 0; i < 4; i++)
#pragma unroll
            for (int j = 0; j < 4; j++) {
                float s = sc[i][j] * 0.125f;
                if (diag && (dx + j > ry + i)) s = -1e9f;
                sc[i][j] = s;
            }

        // Row max across 16-lane group
        float rmax[4];
#pragma unroll
        for (int i = 0; i < 4; i++)
            rmax[i] = fmaxf(fmaxf(sc[i][0], sc[i][1]), fmaxf(sc[i][2], sc[i][3]));
#pragma unroll
        for (int off = 8; off >= 1; off >>= 1)
#pragma unroll
            for (int i = 0; i < 4; i++)
                rmax[i] = fmaxf(rmax[i], __shfl_xor_sync(0xffffffffu, rmax[i], off));

        float al[4], rsum[4];
#pragma unroll
        for (int i = 0; i < 4; i++) {
            float mn = fmaxf(m_[i], rmax[i]);
            al[i] = __expf(m_[i] - mn);
            m_[i] = mn;
            float rs = 0.0f;
#pragma unroll
            for (int j = 0; j < 4; j++) {
                float p = __expf(sc[i][j] - mn);
                sc[i][j] = p;
                rs += p;
            }
            rsum[i] = rs;
        }
#pragma unroll
        for (int off = 8; off >= 1; off >>= 1)
#pragma unroll
            for (int i = 0; i < 4; i++)
                rsum[i] += __shfl_xor_sync(0xffffffffu, rsum[i], off);
#pragma unroll
        for (int i = 0; i < 4; i++) {
            l_[i] = l_[i] * al[i] + rsum[i];
#pragma unroll
            for (int j = 0; j < 4; j++) acc[i][j] *= al[i];
        }

        // Stage P in smem (only this warp's 16-lane group reads these rows)
#pragma unroll
        for (int i = 0; i < 4; i++)
            *(float4*)&Ps[(ry + i) * 64 + dx] =
                make_float4(sc[i][0], sc[i][1], sc[i][2], sc[i][3]);
        __syncwarp();

        // PV: acc[i][j] += sum_kk P[ry+i][kk] * V[kk][dx+j]
        for (int kk = 0; kk < BK; kk++) {
            float b0 = Vs[kk * 65 + dx + 0];
            float b1 = Vs[kk * 65 + dx + 1];
            float b2 = Vs[kk * 65 + dx + 2];
            float b3 = Vs[kk * 65 + dx + 3];
            float a0 = Ps[(ry + 0) * 64 + kk];
            float a1 = Ps[(ry + 1) * 64 + kk];
            float a2 = Ps[(ry + 2) * 64 + kk];
            float a3 = Ps[(ry + 3) * 64 + kk];
            acc[0][0] += a0 * b0; acc[0][1] += a0 * b1; acc[0][2] += a0 * b2; acc[0][3] += a0 * b3;
            acc[1][0] += a1 * b0; acc[1][1] += a1 * b1; acc[1][2] += a1 * b2; acc[1][3] += a1 * b3;
            acc[2][0] += a2 * b0; acc[2][1] += a2 * b1; acc[2][2] += a2 * b2; acc[2][3] += a2 * b3;
            acc[3][0] += a3 * b0; acc[3][1] += a3 * b1; acc[3][2] += a3 * b2; acc[3][3] += a3 * b3;
        }
    }

    // Epilogue: normalize and write O in [S][D] layout
#pragma unroll
    for (int i = 0; i < 4; i++) {
        float inv = 1.0f / l_[i];
        float4 o = make_float4(acc[i][0] * inv, acc[i][1] * inv,
                               acc[i][2] * inv, acc[i][3] * inv);
        *(float4*)&O[(size_t)(q0 + ry + i) * DM + h * HD + dx] = o;
    }
}

// ---------------------------------------------------------------------------
// Launch. Input order (metadata): 0=x, 1=mask(ignored; causal known),
// 2=Wq, 3=Wk, 4=Wv, 5=Wo, 6=bo. Output: float32 [1,4096,768].
// ---------------------------------------------------------------------------
extern "C" void kernel_launch(void* const* d_in, const int* in_sizes, int n_in,
                              void* d_out, int out_size)
{
    (void)in_sizes; (void)n_in; (void)out_size;
    const float* x  = (const float*)d_in[0];
    const float* Wq = (const float*)d_in[2];
    const float* Wk = (const float*)d_in[3];
    const float* Wv = (const float*)d_in[4];
    const float* Wo = (const float*)d_in[5];
    const float* bo = (const float*)d_in[6];
    float* out = (float*)d_out;

    float *Qp, *Kp, *Vp, *AO;
    cudaGetSymbolAddress((void**)&Qp, g_Q);
    cudaGetSymbolAddress((void**)&Kp, g_K);
    cudaGetSymbolAddress((void**)&Vp, g_V);
    cudaGetSymbolAddress((void**)&AO, g_AO);

    cudaFuncSetAttribute(flash_attn,
                         cudaFuncAttributeMaxDynamicSharedMemorySize, SMEM_BYTES);

    dim3 gb(DM / 64, SEQ / 64);
    gemm_nt<false><<<gb, 256>>>(x, Wq, nullptr, Qp, SEQ, DM, DM);
    gemm_nt<false><<<gb, 256>>>(x, Wk, nullptr, Kp, SEQ, DM, DM);
    gemm_nt<false><<<gb, 256>>>(x, Wv, nullptr, Vp, SEQ, DM, DM);

    rope_kernel<<<(SEQ * NH * 32) / 256, 256>>>(Qp, Kp);

    flash_attn<<<dim3(SEQ / BQ, NH), 256, SMEM_BYTES>>>(Qp, Kp, Vp, AO);

    gemm_nt<true><<<gb, 256>>>(AO, Wo, bo, out, SEQ, DM, DM);
}

// round 2
// speedup vs baseline: 3.1218x; 3.1218x over previous
#include <cuda_runtime.h>
#include <cstdint>
#include <math.h>

#define SEQ 4096
#define DM  768
#define NH  12
#define HD  64

// Scratch (allocation-free rule: __device__ globals)
__device__ float  g_Q[SEQ * DM];
__device__ float  g_K[SEQ * DM];
__device__ float  g_V[SEQ * DM];
__device__ float  g_AO[SEQ * DM];
__device__ float2 g_rope[SEQ * 32];   // (cos, sin) per (s, freq)

__device__ __forceinline__ float tf32r(float x) {
    float r; asm("cvt.rna.tf32.f32 %0, %1;" : "=f"(r) : "f"(x)); return r;
}

__device__ __forceinline__ void mma8(float c[4], const uint32_t a[4],
                                     uint32_t b0, uint32_t b1) {
    asm volatile(
        "mma.sync.aligned.m16n8k8.row.col.f32.tf32.tf32.f32 "
        "{%0,%1,%2,%3}, {%4,%5,%6,%7}, {%8,%9}, {%0,%1,%2,%3};"
        : "+f"(c[0]), "+f"(c[1]), "+f"(c[2]), "+f"(c[3])
        : "r"(a[0]), "r"(a[1]), "r"(a[2]), "r"(a[3]), "r"(b0), "r"(b1));
}

// ---------------------------------------------------------------------------
// RoPE tables: accurate inv_freq (double), fp32 angle (matches JAX rounding)
// ---------------------------------------------------------------------------
__global__ __launch_bounds__(256) void rope_table_kernel() {
    int i = blockIdx.x * 256 + threadIdx.x;        // SEQ*32 threads
    int s = i >> 5, d = i & 31;
    float inv = (float)exp(-(double)(2 * d) / 64.0 * log(10000.0));
    float ang = (float)s * inv;
    float sn, cs;
    sincosf(ang, &sn, &cs);
    g_rope[i] = make_float2(cs, sn);
}

// RoPE apply (split-halves layout): one warp per (s, h)
__global__ __launch_bounds__(256) void rope_kernel(float* __restrict__ Q,
                                                   float* __restrict__ Kp) {
    int gw   = (blockIdx.x * 256 + threadIdx.x) >> 5;
    int lane = threadIdx.x & 31;
    if (gw >= SEQ * NH) return;
    int s = gw / NH, h = gw % NH;
    float2 cs = g_rope[s * 32 + lane];

    float* q = Q  + (size_t)s * DM + h * HD;
    float* k = Kp + (size_t)s * DM + h * HD;
    float2 qv = *(const float2*)(q + 2 * lane);
    float2 kv = *(const float2*)(k + 2 * lane);
    __syncwarp();
    q[lane]      = qv.x * cs.x - qv.y * cs.y;
    q[lane + 32] = qv.x * cs.y + qv.y * cs.x;
    k[lane]      = kv.x * cs.x - kv.y * cs.y;
    k[lane + 32] = kv.x * cs.y + kv.y * cs.x;
}

// ---------------------------------------------------------------------------
// TF32 GEMM: C[M,N] = A[M,K] @ B[N,K]^T (+bias). 128x128x32 tiles, 8 warps.
// Warp tile 64x32 (4 m-tiles x 4 n-tiles of m16n8k8).
// smem stride 36 -> fragment gather banks (4g+tg)%32, conflict-free.
// ---------------------------------------------------------------------------
template <bool HAS_BIAS>
__global__ __launch_bounds__(256) void gemm_tf32(
    const float* __restrict__ A, const float* __restrict__ B,
    const float* __restrict__ bias, float* __restrict__ C,
    int M, int N, int K)
{
    __shared__ float As[128][36];
    __shared__ float Bs[128][36];

    const int m0 = blockIdx.y * 128, n0 = blockIdx.x * 128;
    const int t = threadIdx.x, lane = t & 31, wid = t >> 5;
    const int g = lane >> 2, tg = lane & 3;
    const int wm = (wid & 1) * 64, wn = (wid >> 1) * 32;

    float acc[4][4][4];
#pragma unroll
    for (int mi = 0; mi < 4; mi++)
#pragma unroll
        for (int ni = 0; ni < 4; ni++)
#pragma unroll
            for (int c = 0; c < 4; c++) acc[mi][ni][c] = 0.0f;

    for (int k0 = 0; k0 < K; k0 += 32) {
        float4 a_st[4], b_st[4];
#pragma unroll
        for (int i = 0; i < 4; i++) {
            int lin = i * 256 + t, r = lin >> 3, c = (lin & 7) << 2;
            a_st[i] = *(const float4*)&A[(size_t)(m0 + r) * K + k0 + c];
            b_st[i] = *(const float4*)&B[(size_t)(n0 + r) * K + k0 + c];
        }
        __syncthreads();
#pragma unroll
        for (int i = 0; i < 4; i++) {
            int lin = i * 256 + t, r = lin >> 3, c = (lin & 7) << 2;
            *(float4*)&As[r][c] = make_float4(tf32r(a_st[i].x), tf32r(a_st[i].y),
                                              tf32r(a_st[i].z), tf32r(a_st[i].w));
            *(float4*)&Bs[r][c] = make_float4(tf32r(b_st[i].x), tf32r(b_st[i].y),
                                              tf32r(b_st[i].z), tf32r(b_st[i].w));
        }
        __syncthreads();

#pragma unroll
        for (int ks = 0; ks < 4; ks++) {
            const int kb = ks * 8;
            uint32_t af[4][4], bf[4][2];
#pragma unroll
            for (int mi = 0; mi < 4; mi++) {
                int rb = wm + mi * 16;
                af[mi][0] = __float_as_uint(As[rb + g][kb + tg]);
                af[mi][1] = __float_as_uint(As[rb + g + 8][kb + tg]);
                af[mi][2] = __float_as_uint(As[rb + g][kb + tg + 4]);
                af[mi][3] = __float_as_uint(As[rb + g + 8][kb + tg + 4]);
            }
#pragma unroll
            for (int ni = 0; ni < 4; ni++) {
                int cb = wn + ni * 8;
                bf[ni][0] = __float_as_uint(Bs[cb + g][kb + tg]);
                bf[ni][1] = __float_as_uint(Bs[cb + g][kb + tg + 4]);
            }
#pragma unroll
            for (int mi = 0; mi < 4; mi++)
#pragma unroll
                for (int ni = 0; ni < 4; ni++)
                    mma8(acc[mi][ni], af[mi], bf[ni][0], bf[ni][1]);
        }
    }

#pragma unroll
    for (int mi = 0; mi < 4; mi++) {
        int r = m0 + wm + mi * 16 + g;
#pragma unroll
        for (int ni = 0; ni < 4; ni++) {
            int c = n0 + wn + ni * 8 + 2 * tg;
            float bx = 0.f, by = 0.f;
            if (HAS_BIAS) { bx = bias[c]; by = bias[c + 1]; }
            *(float2*)&C[(size_t)r * N + c] =
                make_float2(acc[mi][ni][0] + bx, acc[mi][ni][1] + by);
            *(float2*)&C[(size_t)(r + 8) * N + c] =
                make_float2(acc[mi][ni][2] + bx, acc[mi][ni][3] + by);
        }
    }
}

// ---------------------------------------------------------------------------
// Flash attention, tf32 mma, causal. BQ=BK=64, 128 threads (4 warps).
// Warp w owns q rows [w*16, w*16+16). Q fragments register-resident.
// ---------------------------------------------------------------------------
#define QS 68
#define KSS 68
#define VSS 72
#define PSS 68
#define ATT_SMEM ((64 * QS + 64 * KSS + 64 * VSS + 64 * PSS) * 4)

__global__ __launch_bounds__(128) void flash_tf32(
    const float* __restrict__ Q, const float* __restrict__ K,
    const float* __restrict__ V, float* __restrict__ O)
{
    extern __shared__ float sm[];
    float* Qs = sm;                   // [64][68]
    float* Ks = Qs + 64 * QS;         // [64][68]
    float* Vs = Ks + 64 * KSS;        // [64][72]
    float* Ps = Vs + 64 * VSS;        // [64][68]

    const int h  = blockIdx.y;
    const int qb = gridDim.x - 1 - blockIdx.x;  // long causal rows first
    const int q0 = qb * 64;
    const int t = threadIdx.x, lane = t & 31, w = t >> 5;
    const int g = lane >> 2, tg = lane & 3;

    // Load Q tile (tf32-rounded)
#pragma unroll
    for (int i = 0; i < 8; i++) {
        int lin = i * 128 + t, r = lin >> 4, c = (lin & 15) << 2;
        float4 v = *(const float4*)&Q[(size_t)(q0 + r) * DM + h * HD + c];
        Qs[r * QS + c + 0] = tf32r(v.x);
        Qs[r * QS + c + 1] = tf32r(v.y);
        Qs[r * QS + c + 2] = tf32r(v.z);
        Qs[r * QS + c + 3] = tf32r(v.w);
    }
    __syncthreads();

    // Q fragments, register-resident for the whole KV loop
    uint32_t qf[8][4];
#pragma unroll
    for (int ks = 0; ks < 8; ks++) {
        int rb = w * 16, kb = ks * 8;
        qf[ks][0] = __float_as_uint(Qs[(rb + g) * QS + kb + tg]);
        qf[ks][1] = __float_as_uint(Qs[(rb + g + 8) * QS + kb + tg]);
        qf[ks][2] = __float_as_uint(Qs[(rb + g) * QS + kb + tg + 4]);
        qf[ks][3] = __float_as_uint(Qs[(rb + g + 8) * QS + kb + tg + 4]);
    }

    float m0r = -1e30f, m1r = -1e30f, l0 = 0.0f, l1 = 0.0f;
    float ao[8][4];
#pragma unroll
    for (int nt = 0; nt < 8; nt++)
#pragma unroll
        for (int c = 0; c < 4; c++) ao[nt][c] = 0.0f;

    for (int jb = 0; jb <= qb; jb++) {
        const int k0 = jb * 64;
        __syncthreads();   // previous K/V tiles fully consumed
#pragma unroll
        for (int i = 0; i < 8; i++) {
            int lin = i * 128 + t, r = lin >> 4, c = (lin & 15) << 2;
            float4 kv = *(const float4*)&K[(size_t)(k0 + r) * DM + h * HD + c];
            float4 vv = *(const float4*)&V[(size_t)(k0 + r) * DM + h * HD + c];
            Ks[r * KSS + c + 0] = tf32r(kv.x);
            Ks[r * KSS + c + 1] = tf32r(kv.y);
            Ks[r * KSS + c + 2] = tf32r(kv.z);
            Ks[r * KSS + c + 3] = tf32r(kv.w);
            Vs[r * VSS + c + 0] = tf32r(vv.x);
            Vs[r * VSS + c + 1] = tf32r(vv.y);
            Vs[r * VSS + c + 2] = tf32r(vv.z);
            Vs[r * VSS + c + 3] = tf32r(vv.w);
        }
        __syncthreads();

        // S = Q K^T : sc[nt] covers kv cols [nt*8, nt*8+8)
        float sc[8][4];
#pragma unroll
        for (int nt = 0; nt < 8; nt++)
#pragma unroll
            for (int c = 0; c < 4; c++) sc[nt][c] = 0.0f;

#pragma unroll
        for (int ks = 0; ks < 8; ks++) {
            const int kb = ks * 8;
#pragma unroll
            for (int nt = 0; nt < 8; nt++) {
                uint32_t b0 = __float_as_uint(Ks[(nt * 8 + g) * KSS + kb + tg]);
                uint32_t b1 = __float_as_uint(Ks[(nt * 8 + g) * KSS + kb + tg + 4]);
                mma8(sc[nt], qf[ks], b0, b1);
            }
        }

        // scale + causal mask (reference's exact -1e9 sentinel)
        const float scl = 0.125f;
        if (jb == qb) {
            int i0 = w * 16 + g, i1 = i0 + 8;
#pragma unroll
            for (int nt = 0; nt < 8; nt++) {
                int c0 = nt * 8 + 2 * tg, c1 = c0 + 1;
                sc[nt][0] = (c0 <= i0) ? sc[nt][0] * scl : -1e9f;
                sc[nt][1] = (c1 <= i0) ? sc[nt][1] * scl : -1e9f;
                sc[nt][2] = (c0 <= i1) ? sc[nt][2] * scl : -1e9f;
                sc[nt][3] = (c1 <= i1) ? sc[nt][3] * scl : -1e9f;
            }
        } else {
#pragma unroll
            for (int nt = 0; nt < 8; nt++)
#pragma unroll
                for (int c = 0; c < 4; c++) sc[nt][c] *= scl;
        }

        // online softmax: rows r0 (c0,c1) and r1 (c2,c3), owned by 4 lanes
        float mx0 = -1e30f, mx1 = -1e30f;
#pragma unroll
        for (int nt = 0; nt < 8; nt++) {
            mx0 = fmaxf(mx0, fmaxf(sc[nt][0], sc[nt][1]));
            mx1 = fmaxf(mx1, fmaxf(sc[nt][2], sc[nt][3]));
        }
        mx0 = fmaxf(mx0, __shfl_xor_sync(0xffffffffu, mx0, 1));
        mx0 = fmaxf(mx0, __shfl_xor_sync(0xffffffffu, mx0, 2));
        mx1 = fmaxf(mx1, __shfl_xor_sync(0xffffffffu, mx1, 1));
        mx1 = fmaxf(mx1, __shfl_xor_sync(0xffffffffu, mx1, 2));

        float mn0 = fmaxf(m0r, mx0), mn1 = fmaxf(m1r, mx1);
        float al0 = __expf(m0r - mn0), al1 = __expf(m1r - mn1);
        m0r = mn0; m1r = mn1;

        float rs0 = 0.0f, rs1 = 0.0f;
#pragma unroll
        for (int nt = 0; nt < 8; nt++) {
            sc[nt][0] = __expf(sc[nt][0] - mn0);
            sc[nt][1] = __expf(sc[nt][1] - mn0);
            sc[nt][2] = __expf(sc[nt][2] - mn1);
            sc[nt][3] = __expf(sc[nt][3] - mn1);
            rs0 += sc[nt][0] + sc[nt][1];
            rs1 += sc[nt][2] + sc[nt][3];
        }
        rs0 += __shfl_xor_sync(0xffffffffu, rs0, 1);
        rs0 += __shfl_xor_sync(0xffffffffu, rs0, 2);
        rs1 += __shfl_xor_sync(0xffffffffu, rs1, 1);
        rs1 += __shfl_xor_sync(0xffffffffu, rs1, 2);
        l0 = l0 * al0 + rs0;
        l1 = l1 * al1 + rs1;
#pragma unroll
        for (int nt = 0; nt < 8; nt++) {
            ao[nt][0] *= al0; ao[nt][1] *= al0;
            ao[nt][2] *= al1; ao[nt][3] *= al1;
        }

        // stage P in smem (tf32), per-warp rows only
        {
            int pr0 = w * 16 + g, pr1 = pr0 + 8;
#pragma unroll
            for (int nt = 0; nt < 8; nt++) {
                int c = nt * 8 + 2 * tg;
                Ps[pr0 * PSS + c]     = tf32r(sc[nt][0]);
                Ps[pr0 * PSS + c + 1] = tf32r(sc[nt][1]);
                Ps[pr1 * PSS + c]     = tf32r(sc[nt][2]);
                Ps[pr1 * PSS + c + 1] = tf32r(sc[nt][3]);
            }
        }
        __syncwarp();

        // O += P V
#pragma unroll
        for (int ks = 0; ks < 8; ks++) {
            const int kb = ks * 8;
            uint32_t pf[4];
            pf[0] = __float_as_uint(Ps[(w * 16 + g) * PSS + kb + tg]);
            pf[1] = __float_as_uint(Ps[(w * 16 + g + 8) * PSS + kb + tg]);
            pf[2] = __float_as_uint(Ps[(w * 16 + g) * PSS + kb + tg + 4]);
            pf[3] = __float_as_uint(Ps[(w * 16 + g + 8) * PSS + kb + tg + 4]);
#pragma unroll
            for (int nt = 0; nt < 8; nt++) {
                uint32_t b0 = __float_as_uint(Vs[(kb + tg) * VSS + nt * 8 + g]);
                uint32_t b1 = __float_as_uint(Vs[(kb + tg + 4) * VSS + nt * 8 + g]);
                mma8(ao[nt], pf, b0, b1);
            }
        }
    }

    // epilogue
    float inv0 = 1.0f / l0, inv1 = 1.0f / l1;
    int r0 = q0 + w * 16 + g, r1 = r0 + 8;
#pragma unroll
    for (int nt = 0; nt < 8; nt++) {
        int c = nt * 8 + 2 * tg;
        *(float2*)&O[(size_t)r0 * DM + h * HD + c] =
            make_float2(ao[nt][0] * inv0, ao[nt][1] * inv0);
        *(float2*)&O[(size_t)r1 * DM + h * HD + c] =
            make_float2(ao[nt][2] * inv1, ao[nt][3] * inv1);
    }
}

// ---------------------------------------------------------------------------
// Launch
// ---------------------------------------------------------------------------
extern "C" void kernel_launch(void* const* d_in, const int* in_sizes, int n_in,
                              void* d_out, int out_size)
{
    (void)in_sizes; (void)n_in; (void)out_size;
    const float* x  = (const float*)d_in[0];
    const float* Wq = (const float*)d_in[2];
    const float* Wk = (const float*)d_in[3];
    const float* Wv = (const float*)d_in[4];
    const float* Wo = (const float*)d_in[5];
    const float* bo = (const float*)d_in[6];
    float* out = (float*)d_out;

    float *Qp, *Kp, *Vp, *AO;
    cudaGetSymbolAddress((void**)&Qp, g_Q);
    cudaGetSymbolAddress((void**)&Kp, g_K);
    cudaGetSymbolAddress((void**)&Vp, g_V);
    cudaGetSymbolAddress((void**)&AO, g_AO);

    cudaFuncSetAttribute(flash_tf32,
                         cudaFuncAttributeMaxDynamicSharedMemorySize, ATT_SMEM);

    dim3 gb(DM / 128, SEQ / 128);
    gemm_tf32<false><<<gb, 256>>>(x, Wq, nullptr, Qp, SEQ, DM, DM);
    gemm_tf32<false><<<gb, 256>>>(x, Wk, nullptr, Kp, SEQ, DM, DM);
    gemm_tf32<false><<<gb, 256>>>(x, Wv, nullptr, Vp, SEQ, DM, DM);

    rope_table_kernel<<<(SEQ * 32) / 256, 256>>>();
    rope_kernel<<<(SEQ * NH * 32) / 256, 256>>>(Qp, Kp);

    flash_tf32<<<dim3(SEQ / 64, NH), 128, ATT_SMEM>>>(Qp, Kp, Vp, AO);

    gemm_tf32<true><<<gb, 256>>>(AO, Wo, bo, out, SEQ, DM, DM);
}

// round 5
// speedup vs baseline: 3.8806x; 1.2431x over previous
#include <cuda_runtime.h>
#include <cstdint>
#include <math.h>

#define SEQ 4096
#define DM  768
#define NH  12
#define HD  64

// Scratch (allocation-free rule: __device__ globals)
__device__ float  g_Q[SEQ * DM];
__device__ float  g_K[SEQ * DM];
__device__ float  g_V[SEQ * DM];
__device__ float  g_AO[SEQ * DM];
__device__ float  g_invf[32];
__device__ float2 g_rope[SEQ * 32];

__device__ __forceinline__ float tf32r(float x) {
    float r; asm("cvt.rna.tf32.f32 %0, %1;" : "=f"(r) : "f"(x)); return r;
}
__device__ __forceinline__ void mma8(float c[4], const uint32_t a[4],
                                     uint32_t b0, uint32_t b1) {
    asm volatile(
        "mma.sync.aligned.m16n8k8.row.col.f32.tf32.tf32.f32 "
        "{%0,%1,%2,%3}, {%4,%5,%6,%7}, {%8,%9}, {%0,%1,%2,%3};"
        : "+f"(c[0]), "+f"(c[1]), "+f"(c[2]), "+f"(c[3])
        : "r"(a[0]), "r"(a[1]), "r"(a[2]), "r"(a[3]), "r"(b0), "r"(b1));
}

// ---------------------------------------------------------------------------
// RoPE: 32-thread double-precision inv_freq, then fp32 table, then apply
// ---------------------------------------------------------------------------
__global__ void invfreq_kernel() {
    int d = threadIdx.x;   // 32 threads
    g_invf[d] = (float)exp(-(double)(2 * d) / 64.0 * log(10000.0));
}

__global__ __launch_bounds__(256) void rope_table_kernel() {
    int i = blockIdx.x * 256 + threadIdx.x;   // SEQ*32 threads
    int s = i >> 5, d = i & 31;
    float ang = (float)s * g_invf[d];
    float sn, cs;
    sincosf(ang, &sn, &cs);
    g_rope[i] = make_float2(cs, sn);
}

__global__ __launch_bounds__(256) void rope_kernel(float* __restrict__ Q,
                                                   float* __restrict__ Kp) {
    int gw   = (blockIdx.x * 256 + threadIdx.x) >> 5;
    int lane = threadIdx.x & 31;
    if (gw >= SEQ * NH) return;
    int s = gw / NH, h = gw % NH;
    float2 cs = g_rope[s * 32 + lane];

    float* q = Q  + (size_t)s * DM + h * HD;
    float* k = Kp + (size_t)s * DM + h * HD;
    float2 qv = *(const float2*)(q + 2 * lane);
    float2 kv = *(const float2*)(k + 2 * lane);
    __syncwarp();
    q[lane]      = qv.x * cs.x - qv.y * cs.y;
    q[lane + 32] = qv.x * cs.y + qv.y * cs.x;
    k[lane]      = kv.x * cs.x - kv.y * cs.y;
    k[lane + 32] = kv.x * cs.y + kv.y * cs.x;
}

// ---------------------------------------------------------------------------
// TF32 GEMM (mma.sync), software-pipelined global loads.
// C[M, DM] = A[M, DM] @ W[DM, DM]^T (+bias); QKV fused via W0/W1/W2 select.
// 128x128 tile/CTA, k-slab 32, 256 threads, warp tile 64x32.
// ---------------------------------------------------------------------------
template <bool HAS_BIAS>
__global__ __launch_bounds__(256) void gemm_tf32(
    const float* __restrict__ A,
    const float* __restrict__ W0, const float* __restrict__ W1,
    const float* __restrict__ W2,
    const float* __restrict__ bias,
    float* __restrict__ C0, float* __restrict__ C1, float* __restrict__ C2)
{
    __shared__ float As[128][36];
    __shared__ float Bs[128][36];

    const int m0  = blockIdx.y * 128;
    const int nt  = blockIdx.x;
    const int mat = nt / 6;
    const int n0  = (nt % 6) * 128;
    const float* W = (mat == 0) ? W0 : (mat == 1) ? W1 : W2;
    float*       C = (mat == 0) ? C0 : (mat == 1) ? C1 : C2;

    const int t = threadIdx.x, lane = t & 31, wid = t >> 5;
    const int g = lane >> 2, tg = lane & 3;
    const int wm = (wid & 1) * 64, wn = (wid >> 1) * 32;

    float acc[4][4][4];
#pragma unroll
    for (int mi = 0; mi < 4; mi++)
#pragma unroll
        for (int ni = 0; ni < 4; ni++)
#pragma unroll
            for (int c = 0; c < 4; c++) acc[mi][ni][c] = 0.0f;

    const int r_ld = t >> 3;          // 0..31 step: u>>3 covers 0..127 over 4 its
    const int c_ld = (t & 7) << 2;    // 0,4,...,28

    float4 a_pf[4], b_pf[4];
    // prefetch slab 0
#pragma unroll
    for (int it = 0; it < 4; it++) {
        int r = it * 32 + r_ld;
        a_pf[it] = *(const float4*)&A[(size_t)(m0 + r) * DM + c_ld];
        b_pf[it] = *(const float4*)&W[(size_t)(n0 + r) * DM + c_ld];
    }

    for (int i = 0; i < 24; i++) {
        __syncthreads();
#pragma unroll
        for (int it = 0; it < 4; it++) {
            int r = it * 32 + r_ld;
            *(float4*)&As[r][c_ld] = make_float4(tf32r(a_pf[it].x), tf32r(a_pf[it].y),
                                                 tf32r(a_pf[it].z), tf32r(a_pf[it].w));
            *(float4*)&Bs[r][c_ld] = make_float4(tf32r(b_pf[it].x), tf32r(b_pf[it].y),
                                                 tf32r(b_pf[it].z), tf32r(b_pf[it].w));
        }
        __syncthreads();
        if (i < 23) {
            const int k0 = (i + 1) * 32;
#pragma unroll
            for (int it = 0; it < 4; it++) {
                int r = it * 32 + r_ld;
                a_pf[it] = *(const float4*)&A[(size_t)(m0 + r) * DM + k0 + c_ld];
                b_pf[it] = *(const float4*)&W[(size_t)(n0 + r) * DM + k0 + c_ld];
            }
        }
#pragma unroll
        for (int ks = 0; ks < 4; ks++) {
            const int kb = ks * 8;
            uint32_t af[4][4], bf[4][2];
#pragma unroll
            for (int mi = 0; mi < 4; mi++) {
                int rb = wm + mi * 16;
                af[mi][0] = __float_as_uint(As[rb + g][kb + tg]);
                af[mi][1] = __float_as_uint(As[rb + g + 8][kb + tg]);
                af[mi][2] = __float_as_uint(As[rb + g][kb + tg + 4]);
                af[mi][3] = __float_as_uint(As[rb + g + 8][kb + tg + 4]);
            }
#pragma unroll
            for (int ni = 0; ni < 4; ni++) {
                int cb = wn + ni * 8;
                bf[ni][0] = __float_as_uint(Bs[cb + g][kb + tg]);
                bf[ni][1] = __float_as_uint(Bs[cb + g][kb + tg + 4]);
            }
#pragma unroll
            for (int mi = 0; mi < 4; mi++)
#pragma unroll
                for (int ni = 0; ni < 4; ni++)
                    mma8(acc[mi][ni], af[mi], bf[ni][0], bf[ni][1]);
        }
    }

#pragma unroll
    for (int mi = 0; mi < 4; mi++) {
        int r = m0 + wm + mi * 16 + g;
#pragma unroll
        for (int ni = 0; ni < 4; ni++) {
            int c = n0 + wn + ni * 8 + 2 * tg;
            float bx = 0.f, by = 0.f;
            if (HAS_BIAS) { bx = bias[c]; by = bias[c + 1]; }
            *(float2*)&C[(size_t)r * DM + c] =
                make_float2(acc[mi][ni][0] + bx, acc[mi][ni][1] + by);
            *(float2*)&C[(size_t)(r + 8) * DM + c] =
                make_float2(acc[mi][ni][2] + bx, acc[mi][ni][3] + by);
        }
    }
}

// ---------------------------------------------------------------------------
// Flash attention, tf32 mma.sync, causal. BQ=128, BK=64, 256 threads (8 warps).
// Warp w owns q rows [w*16, w*16+16). Numerics identical to round 2.
// ---------------------------------------------------------------------------
#define BQF 128
#define QS  68
#define KSS 68
#define VSS 72
#define PSS 68
#define ATT_SMEM ((BQF * QS + 64 * KSS + 64 * VSS + BQF * PSS) * 4)

__global__ __launch_bounds__(256, 2) void flash_tf32(
    const float* __restrict__ Q, const float* __restrict__ K,
    const float* __restrict__ V, float* __restrict__ O)
{
    extern __shared__ float sm[];
    float* Qs = sm;                    // [128][68]
    float* Ks = Qs + BQF * QS;         // [64][68]
    float* Vs = Ks + 64 * KSS;         // [64][72]
    float* Ps = Vs + 64 * VSS;         // [128][68]

    const int h  = blockIdx.y;
    const int qb = gridDim.x - 1 - blockIdx.x;   // long causal rows first
    const int q0 = qb * BQF;
    const int t = threadIdx.x, lane = t & 31, w = t >> 5;
    const int g = lane >> 2, tg = lane & 3;

    // Load Q tile (128 rows), tf32-rounded
#pragma unroll
    for (int i = 0; i < 8; i++) {
        int lin = i * 256 + t, r = lin >> 4, c = (lin & 15) << 2;
        float4 v = *(const float4*)&Q[(size_t)(q0 + r) * DM + h * HD + c];
        Qs[r * QS + c + 0] = tf32r(v.x);
        Qs[r * QS + c + 1] = tf32r(v.y);
        Qs[r * QS + c + 2] = tf32r(v.z);
        Qs[r * QS + c + 3] = tf32r(v.w);
    }
    __syncthreads();

    // Q fragments register-resident
    uint32_t qf[8][4];
#pragma unroll
    for (int ks = 0; ks < 8; ks++) {
        int rb = w * 16, kb = ks * 8;
        qf[ks][0] = __float_as_uint(Qs[(rb + g) * QS + kb + tg]);
        qf[ks][1] = __float_as_uint(Qs[(rb + g + 8) * QS + kb + tg]);
        qf[ks][2] = __float_as_uint(Qs[(rb + g) * QS + kb + tg + 4]);
        qf[ks][3] = __float_as_uint(Qs[(rb + g + 8) * QS + kb + tg + 4]);
    }

    float m0r = -1e30f, m1r = -1e30f, l0 = 0.0f, l1 = 0.0f;
    float ao[8][4];
#pragma unroll
    for (int nt = 0; nt < 8; nt++)
#pragma unroll
        for (int c = 0; c < 4; c++) ao[nt][c] = 0.0f;

    const int jbmax = 2 * qb + 1;
    for (int jb = 0; jb <= jbmax; jb++) {
        const int k0 = jb * 64;
        __syncthreads();   // previous K/V tiles fully consumed
#pragma unroll
        for (int i = 0; i < 4; i++) {
            int lin = i * 256 + t, r = lin >> 4, c = (lin & 15) << 2;
            float4 kv = *(const float4*)&K[(size_t)(k0 + r) * DM + h * HD + c];
            float4 vv = *(const float4*)&V[(size_t)(k0 + r) * DM + h * HD + c];
            Ks[r * KSS + c + 0] = tf32r(kv.x);
            Ks[r * KSS + c + 1] = tf32r(kv.y);
            Ks[r * KSS + c + 2] = tf32r(kv.z);
            Ks[r * KSS + c + 3] = tf32r(kv.w);
            Vs[r * VSS + c + 0] = tf32r(vv.x);
            Vs[r * VSS + c + 1] = tf32r(vv.y);
            Vs[r * VSS + c + 2] = tf32r(vv.z);
            Vs[r * VSS + c + 3] = tf32r(vv.w);
        }
        __syncthreads();

        // S = Q K^T
        float sc[8][4];
#pragma unroll
        for (int nt = 0; nt < 8; nt++)
#pragma unroll
            for (int c = 0; c < 4; c++) sc[nt][c] = 0.0f;

#pragma unroll
        for (int ks = 0; ks < 8; ks++) {
            const int kb = ks * 8;
#pragma unroll
            for (int nt = 0; nt < 8; nt++) {
                uint32_t b0 = __float_as_uint(Ks[(nt * 8 + g) * KSS + kb + tg]);
                uint32_t b1 = __float_as_uint(Ks[(nt * 8 + g) * KSS + kb + tg + 4]);
                mma8(sc[nt], qf[ks], b0, b1);
            }
        }

        // scale + causal mask (mask only when this kv block can cross diagonal)
        const float scl = 0.125f;
        const int off = k0 - q0;       // -..., 0, or 64
        if (off >= 0) {
            int lim0 = w * 16 + g - off, lim1 = lim0 + 8;
#pragma unroll
            for (int nt = 0; nt < 8; nt++) {
                int c0 = nt * 8 + 2 * tg, c1 = c0 + 1;
                sc[nt][0] = (c0 <= lim0) ? sc[nt][0] * scl : -1e9f;
                sc[nt][1] = (c1 <= lim0) ? sc[nt][1] * scl : -1e9f;
                sc[nt][2] = (c0 <= lim1) ? sc[nt][2] * scl : -1e9f;
                sc[nt][3] = (c1 <= lim1) ? sc[nt][3] * scl : -1e9f;
            }
        } else {
#pragma unroll
            for (int nt = 0; nt < 8; nt++)
#pragma unroll
                for (int c = 0; c < 4; c++) sc[nt][c] *= scl;
        }

        // online softmax (rows r0: c0/c1, r1: c2/c3; 4 owner lanes each)
        float mx0 = -1e30f, mx1 = -1e30f;
#pragma unroll
        for (int nt = 0; nt < 8; nt++) {
            mx0 = fmaxf(mx0, fmaxf(sc[nt][0], sc[nt][1]));
            mx1 = fmaxf(mx1, fmaxf(sc[nt][2], sc[nt][3]));
        }
        mx0 = fmaxf(mx0, __shfl_xor_sync(0xffffffffu, mx0, 1));
        mx0 = fmaxf(mx0, __shfl_xor_sync(0xffffffffu, mx0, 2));
        mx1 = fmaxf(mx1, __shfl_xor_sync(0xffffffffu, mx1, 1));
        mx1 = fmaxf(mx1, __shfl_xor_sync(0xffffffffu, mx1, 2));

        float mn0 = fmaxf(m0r, mx0), mn1 = fmaxf(m1r, mx1);
        float al0 = __expf(m0r - mn0), al1 = __expf(m1r - mn1);
        m0r = mn0; m1r = mn1;

        float rs0 = 0.0f, rs1 = 0.0f;
#pragma unroll
        for (int nt = 0; nt < 8; nt++) {
            sc[nt][0] = __expf(sc[nt][0] - mn0);
            sc[nt][1] = __expf(sc[nt][1] - mn0);
            sc[nt][2] = __expf(sc[nt][2] - mn1);
            sc[nt][3] = __expf(sc[nt][3] - mn1);
            rs0 += sc[nt][0] + sc[nt][1];
            rs1 += sc[nt][2] + sc[nt][3];
        }
        rs0 += __shfl_xor_sync(0xffffffffu, rs0, 1);
        rs0 += __shfl_xor_sync(0xffffffffu, rs0, 2);
        rs1 += __shfl_xor_sync(0xffffffffu, rs1, 1);
        rs1 += __shfl_xor_sync(0xffffffffu, rs1, 2);
        l0 = l0 * al0 + rs0;
        l1 = l1 * al1 + rs1;
#pragma unroll
        for (int nt = 0; nt < 8; nt++) {
            ao[nt][0] *= al0; ao[nt][1] *= al0;
            ao[nt][2] *= al1; ao[nt][3] *= al1;
        }

        // stage P (tf32) in per-warp smem rows
        {
            int pr0 = w * 16 + g, pr1 = pr0 + 8;
#pragma unroll
            for (int nt = 0; nt < 8; nt++) {
                int c = nt * 8 + 2 * tg;
                Ps[pr0 * PSS + c]     = tf32r(sc[nt][0]);
                Ps[pr0 * PSS + c + 1] = tf32r(sc[nt][1]);
                Ps[pr1 * PSS + c]     = tf32r(sc[nt][2]);
                Ps[pr1 * PSS + c + 1] = tf32r(sc[nt][3]);
            }
        }
        __syncwarp();

        // O += P V
#pragma unroll
        for (int ks = 0; ks < 8; ks++) {
            const int kb = ks * 8;
            uint32_t pf[4];
            pf[0] = __float_as_uint(Ps[(w * 16 + g) * PSS + kb + tg]);
            pf[1] = __float_as_uint(Ps[(w * 16 + g + 8) * PSS + kb + tg]);
            pf[2] = __float_as_uint(Ps[(w * 16 + g) * PSS + kb + tg + 4]);
            pf[3] = __float_as_uint(Ps[(w * 16 + g + 8) * PSS + kb + tg + 4]);
#pragma unroll
            for (int nt = 0; nt < 8; nt++) {
                uint32_t b0 = __float_as_uint(Vs[(kb + tg) * VSS + nt * 8 + g]);
                uint32_t b1 = __float_as_uint(Vs[(kb + tg + 4) * VSS + nt * 8 + g]);
                mma8(ao[nt], pf, b0, b1);
            }
        }
    }

    // epilogue
    float inv0 = 1.0f / l0, inv1 = 1.0f / l1;
    int r0 = q0 + w * 16 + g, r1 = r0 + 8;
#pragma unroll
    for (int nt = 0; nt < 8; nt++) {
        int c = nt * 8 + 2 * tg;
        *(float2*)&O[(size_t)r0 * DM + h * HD + c] =
            make_float2(ao[nt][0] * inv0, ao[nt][1] * inv0);
        *(float2*)&O[(size_t)r1 * DM + h * HD + c] =
            make_float2(ao[nt][2] * inv1, ao[nt][3] * inv1);
    }
}

// ---------------------------------------------------------------------------
// Launch
// ---------------------------------------------------------------------------
extern "C" void kernel_launch(void* const* d_in, const int* in_sizes, int n_in,
                              void* d_out, int out_size)
{
    (void)in_sizes; (void)n_in; (void)out_size;
    const float* x  = (const float*)d_in[0];
    const float* Wq = (const float*)d_in[2];
    const float* Wk = (const float*)d_in[3];
    const float* Wv = (const float*)d_in[4];
    const float* Wo = (const float*)d_in[5];
    const float* bo = (const float*)d_in[6];
    float* out = (float*)d_out;

    float *Qp, *Kp, *Vp, *AO;
    cudaGetSymbolAddress((void**)&Qp, g_Q);
    cudaGetSymbolAddress((void**)&Kp, g_K);
    cudaGetSymbolAddress((void**)&Vp, g_V);
    cudaGetSymbolAddress((void**)&AO, g_AO);

    cudaFuncSetAttribute(flash_tf32,
                         cudaFuncAttributeMaxDynamicSharedMemorySize, ATT_SMEM);

    // RoPE tables (independent of GEMM, cheap)
    invfreq_kernel<<<1, 32>>>();
    rope_table_kernel<<<(SEQ * 32) / 256, 256>>>();

    // Fused QKV projection
    gemm_tf32<false><<<dim3(18, 32), 256>>>(x, Wq, Wk, Wv, nullptr, Qp, Kp, Vp);

    rope_kernel<<<(SEQ * NH * 32) / 256, 256>>>(Qp, Kp);

    flash_tf32<<<dim3(SEQ / BQF, NH), 256, ATT_SMEM>>>(Qp, Kp, Vp, AO);

    // Output projection + bias
    gemm_tf32<true><<<dim3(6, 32), 256>>>(AO, Wo, Wo, Wo, bo, out, out, out);
}

// round 7
// speedup vs baseline: 4.1490x; 1.0692x over previous
#include <cuda_runtime.h>
#include <cstdint>
#include <math.h>

#define SEQ 4096
#define DM  768
#define NH  12
#define HD  64

// Scratch (allocation-free rule: __device__ globals)
__device__ float  g_Q[SEQ * DM];
__device__ float  g_K[SEQ * DM];
__device__ float  g_V[SEQ * DM];
__device__ float  g_AO[SEQ * DM];
__device__ float  g_invf[32];
__device__ float2 g_rope[SEQ * 32];

__device__ __forceinline__ float tf32r(float x) {
    float r; asm("cvt.rna.tf32.f32 %0, %1;" : "=f"(r) : "f"(x)); return r;
}
__device__ __forceinline__ void mma8(float c[4], const uint32_t a[4],
                                     uint32_t b0, uint32_t b1) {
    asm volatile(
        "mma.sync.aligned.m16n8k8.row.col.f32.tf32.tf32.f32 "
        "{%0,%1,%2,%3}, {%4,%5,%6,%7}, {%8,%9}, {%0,%1,%2,%3};"
        : "+f"(c[0]), "+f"(c[1]), "+f"(c[2]), "+f"(c[3])
        : "r"(a[0]), "r"(a[1]), "r"(a[2]), "r"(a[3]), "r"(b0), "r"(b1));
}
__device__ __forceinline__ uint32_t s2u(const void* p) {
    return (uint32_t)__cvta_generic_to_shared(p);
}
#define CPA16(dst, src) \
    asm volatile("cp.async.ca.shared.global [%0], [%1], 16;" :: "r"(dst), "l"(src))
#define CPA_COMMIT() asm volatile("cp.async.commit_group;" ::: "memory")
#define CPA_WAIT0()  asm volatile("cp.async.wait_group 0;" ::: "memory")
#define CPA_WAIT1()  asm volatile("cp.async.wait_group 1;" ::: "memory")

// ---------------------------------------------------------------------------
// RoPE tables
// ---------------------------------------------------------------------------
__global__ void invfreq_kernel() {
    int d = threadIdx.x;   // 32 threads
    g_invf[d] = (float)exp(-(double)(2 * d) / 64.0 * log(10000.0));
}

__global__ __launch_bounds__(256) void rope_table_kernel() {
    int i = blockIdx.x * 256 + threadIdx.x;   // SEQ*32 threads
    int s = i >> 5, d = i & 31;
    float ang = (float)s * g_invf[d];
    float sn, cs;
    sincosf(ang, &sn, &cs);
    g_rope[i] = make_float2(cs, sn);
}

// ---------------------------------------------------------------------------
// TF32 GEMM (mma.sync), cp.async 3-stage pipeline.
// C = A @ W^T; QKV fused (mat = blockIdx.x/6 selects W/C).
// 128x128 tile/CTA, k-slab 32, 256 threads, warp tile 64x32.
// Epilogue: mat<2 -> RoPE rotate + tf32-round (split-halves layout)
//           mat==2 -> tf32-round (V)      HAS_BIAS -> +bias raw fp32 (final out)
// ---------------------------------------------------------------------------
#define GS_FLOATS (128 * 36)
#define GEMM_SMEM (3 * 2 * GS_FLOATS * 4)

template <bool HAS_BIAS>
__global__ __launch_bounds__(256) void gemm_tf32(
    const float* __restrict__ A,
    const float* __restrict__ W0, const float* __restrict__ W1,
    const float* __restrict__ W2,
    const float* __restrict__ bias,
    float* __restrict__ C0, float* __restrict__ C1, float* __restrict__ C2)
{
    extern __shared__ float gsm[];

    const int m0  = blockIdx.y * 128;
    const int nt  = blockIdx.x;
    const int mat = nt / 6;
    const int n0  = (nt % 6) * 128;
    const float* W = (mat == 0) ? W0 : (mat == 1) ? W1 : W2;
    float*       C = (mat == 0) ? C0 : (mat == 1) ? C1 : C2;

    const int t = threadIdx.x, lane = t & 31, wid = t >> 5;
    const int g = lane >> 2, tg = lane & 3;
    const int wm = (wid & 1) * 64, wn = (wid >> 1) * 32;
    const int r_ld = t >> 3, c_ld = (t & 7) << 2;

    float acc[4][4][4] = {};

    auto issue = [&](int slab) {
        float* As = gsm + (slab % 3) * 2 * GS_FLOATS;
        float* Bs = As + GS_FLOATS;
        const int k0 = slab * 32;
#pragma unroll
        for (int it = 0; it < 4; it++) {
            int r = it * 32 + r_ld;
            CPA16(s2u(&As[r * 36 + c_ld]), &A[(size_t)(m0 + r) * DM + k0 + c_ld]);
            CPA16(s2u(&Bs[r * 36 + c_ld]), &W[(size_t)(n0 + r) * DM + k0 + c_ld]);
        }
        CPA_COMMIT();
    };
    issue(0);
    issue(1);

    for (int i = 0; i < 24; i++) {
        if (i < 22) CPA_WAIT1(); else CPA_WAIT0();
        __syncthreads();
        if (i + 2 < 24) issue(i + 2);

        float* As = gsm + (i % 3) * 2 * GS_FLOATS;
        float* Bs = As + GS_FLOATS;
#pragma unroll
        for (int ks = 0; ks < 4; ks++) {
            const int kb = ks * 8;
            uint32_t af[4][4], bf[4][2];
#pragma unroll
            for (int mi = 0; mi < 4; mi++) {
                int rb = wm + mi * 16;
                af[mi][0] = __float_as_uint(tf32r(As[(rb + g) * 36 + kb + tg]));
                af[mi][1] = __float_as_uint(tf32r(As[(rb + g + 8) * 36 + kb + tg]));
                af[mi][2] = __float_as_uint(tf32r(As[(rb + g) * 36 + kb + tg + 4]));
                af[mi][3] = __float_as_uint(tf32r(As[(rb + g + 8) * 36 + kb + tg + 4]));
            }
#pragma unroll
            for (int ni = 0; ni < 4; ni++) {
                int cb = wn + ni * 8;
                bf[ni][0] = __float_as_uint(tf32r(Bs[(cb + g) * 36 + kb + tg]));
                bf[ni][1] = __float_as_uint(tf32r(Bs[(cb + g) * 36 + kb + tg + 4]));
            }
#pragma unroll
            for (int mi = 0; mi < 4; mi++)
#pragma unroll
                for (int ni = 0; ni < 4; ni++)
                    mma8(acc[mi][ni], af[mi], bf[ni][0], bf[ni][1]);
        }
    }

#pragma unroll
    for (int mi = 0; mi < 4; mi++) {
        int r = m0 + wm + mi * 16 + g;
#pragma unroll
        for (int ni = 0; ni < 4; ni++) {
            int c = n0 + wn + ni * 8 + 2 * tg;   // always even
            float v00 = acc[mi][ni][0], v01 = acc[mi][ni][1];
            float v10 = acc[mi][ni][2], v11 = acc[mi][ni][3];
            if (HAS_BIAS) {
                float bx = bias[c], by = bias[c + 1];
                *(float2*)&C[(size_t)r * DM + c] = make_float2(v00 + bx, v01 + by);
                *(float2*)&C[(size_t)(r + 8) * DM + c] = make_float2(v10 + bx, v11 + by);
            } else if (mat < 2) {
                // RoPE: input pair (x[2d], x[2d+1]) -> out[d], out[d+32]
                int d = (c & 63) >> 1, hb = c & ~63;
                float2 cs0 = g_rope[r * 32 + d];
                float2 cs1 = g_rope[(r + 8) * 32 + d];
                C[(size_t)r * DM + hb + d]            = tf32r(v00 * cs0.x - v01 * cs0.y);
                C[(size_t)r * DM + hb + d + 32]       = tf32r(v00 * cs0.y + v01 * cs0.x);
                C[(size_t)(r + 8) * DM + hb + d]      = tf32r(v10 * cs1.x - v11 * cs1.y);
                C[(size_t)(r + 8) * DM + hb + d + 32] = tf32r(v10 * cs1.y + v11 * cs1.x);
            } else {
                *(float2*)&C[(size_t)r * DM + c] = make_float2(tf32r(v00), tf32r(v01));
                *(float2*)&C[(size_t)(r + 8) * DM + c] = make_float2(tf32r(v10), tf32r(v11));
            }
        }
    }
}

// ---------------------------------------------------------------------------
// Flash attention, tf32 mma.sync, causal. BQ=128, BK=64, 256 threads.
// Q/K/V pre-rounded (+RoPE) in global. cp.async double-buffered K/V;
// stage B reuses the dead Q staging region -> smem 104KB, occupancy 2.
// ---------------------------------------------------------------------------
#define KSS 68
#define VSS 72
#define PSS 68
#define KVSTG 8960                 // floats per KV stage (64*68 + 64*72)
#define PS_OFF (2 * KVSTG)         // 17920
#define ATT_SMEM ((PS_OFF + 128 * PSS) * 4)   // 106496 B

__global__ __launch_bounds__(256, 2) void flash_tf32(
    const float* __restrict__ Q, const float* __restrict__ K,
    const float* __restrict__ V, float* __restrict__ O)
{
    extern __shared__ float sm[];
    const int h  = blockIdx.y;
    const int qb = gridDim.x - 1 - blockIdx.x;   // long causal rows first
    const int q0 = qb * 128;
    const int t = threadIdx.x, lane = t & 31, w = t >> 5;
    const int g = lane >> 2, tg = lane & 3;

    // Issue Q tile into stage-B region (dead after qf extraction)
    {
        float* QB = sm + KVSTG;
#pragma unroll
        for (int it = 0; it < 8; it++) {
            int lin = it * 256 + t, r = lin >> 4, c = (lin & 15) << 2;
            CPA16(s2u(&QB[r * 68 + c]), &Q[(size_t)(q0 + r) * DM + h * HD + c]);
        }
        CPA_COMMIT();
    }
    auto issue_kv = [&](int jb, int st) {
        float* Ks = sm + st * KVSTG;
        float* Vs = Ks + 64 * KSS;
        const int k0 = jb * 64;
#pragma unroll
        for (int it = 0; it < 4; it++) {
            int lin = it * 256 + t, r = lin >> 4, c = (lin & 15) << 2;
            CPA16(s2u(&Ks[r * KSS + c]), &K[(size_t)(k0 + r) * DM + h * HD + c]);
            CPA16(s2u(&Vs[r * VSS + c]), &V[(size_t)(k0 + r) * DM + h * HD + c]);
        }
        CPA_COMMIT();
    };
    issue_kv(0, 0);

    CPA_WAIT1();        // Q group complete (KV0 may still be in flight)
    __syncthreads();

    uint32_t qf[8][4];
    {
        float* QB = sm + KVSTG;
#pragma unroll
        for (int ks = 0; ks < 8; ks++) {
            int rb = w * 16, kb = ks * 8;
            qf[ks][0] = __float_as_uint(QB[(rb + g) * 68 + kb + tg]);
            qf[ks][1] = __float_as_uint(QB[(rb + g + 8) * 68 + kb + tg]);
            qf[ks][2] = __float_as_uint(QB[(rb + g) * 68 + kb + tg + 4]);
            qf[ks][3] = __float_as_uint(QB[(rb + g + 8) * 68 + kb + tg + 4]);
        }
    }

    float m0r = -1e30f, m1r = -1e30f, l0 = 0.0f, l1 = 0.0f;
    float ao[8][4];
#pragma unroll
    for (int nt = 0; nt < 8; nt++)
#pragma unroll
        for (int c = 0; c < 4; c++) ao[nt][c] = 0.0f;

    float* Ps = sm + PS_OFF;
    const int jbmax = 2 * qb + 1;

    for (int jb = 0; jb <= jbmax; jb++) {
        CPA_WAIT0();          // KV(jb) landed
        __syncthreads();      // visible to all; all warps done with prev stage
        if (jb < jbmax) issue_kv(jb + 1, (jb + 1) & 1);

        float* Ks = sm + (jb & 1) * KVSTG;
        float* Vs = Ks + 64 * KSS;
        const int k0 = jb * 64;

        // S = Q K^T
        float sc[8][4];
#pragma unroll
        for (int nt = 0; nt < 8; nt++)
#pragma unroll
            for (int c = 0; c < 4; c++) sc[nt][c] = 0.0f;

#pragma unroll
        for (int ks = 0; ks < 8; ks++) {
            const int kb = ks * 8;
#pragma unroll
            for (int nt = 0; nt < 8; nt++) {
                uint32_t b0 = __float_as_uint(Ks[(nt * 8 + g) * KSS + kb + tg]);
                uint32_t b1 = __float_as_uint(Ks[(nt * 8 + g) * KSS + kb + tg + 4]);
                mma8(sc[nt], qf[ks], b0, b1);
            }
        }

        // scale + causal mask
        const float scl = 0.125f;
        const int off = k0 - q0;
        if (off >= 0) {
            int lim0 = w * 16 + g - off, lim1 = lim0 + 8;
#pragma unroll
            for (int nt = 0; nt < 8; nt++) {
                int c0 = nt * 8 + 2 * tg, c1 = c0 + 1;
                sc[nt][0] = (c0 <= lim0) ? sc[nt][0] * scl : -1e9f;
                sc[nt][1] = (c1 <= lim0) ? sc[nt][1] * scl : -1e9f;
                sc[nt][2] = (c0 <= lim1) ? sc[nt][2] * scl : -1e9f;
                sc[nt][3] = (c1 <= lim1) ? sc[nt][3] * scl : -1e9f;
            }
        } else {
#pragma unroll
            for (int nt = 0; nt < 8; nt++)
#pragma unroll
                for (int c = 0; c < 4; c++) sc[nt][c] *= scl;
        }

        // online softmax
        float mx0 = -1e30f, mx1 = -1e30f;
#pragma unroll
        for (int nt = 0; nt < 8; nt++) {
            mx0 = fmaxf(mx0, fmaxf(sc[nt][0], sc[nt][1]));
            mx1 = fmaxf(mx1, fmaxf(sc[nt][2], sc[nt][3]));
        }
        mx0 = fmaxf(mx0, __shfl_xor_sync(0xffffffffu, mx0, 1));
        mx0 = fmaxf(mx0, __shfl_xor_sync(0xffffffffu, mx0, 2));
        mx1 = fmaxf(mx1, __shfl_xor_sync(0xffffffffu, mx1, 1));
        mx1 = fmaxf(mx1, __shfl_xor_sync(0xffffffffu, mx1, 2));

        float mn0 = fmaxf(m0r, mx0), mn1 = fmaxf(m1r, mx1);
        float al0 = __expf(m0r - mn0), al1 = __expf(m1r - mn1);
        m0r = mn0; m1r = mn1;

        float rs0 = 0.0f, rs1 = 0.0f;
#pragma unroll
        for (int nt = 0; nt < 8; nt++) {
            sc[nt][0] = __expf(sc[nt][0] - mn0);
            sc[nt][1] = __expf(sc[nt][1] - mn0);
            sc[nt][2] = __expf(sc[nt][2] - mn1);
            sc[nt][3] = __expf(sc[nt][3] - mn1);
            rs0 += sc[nt][0] + sc[nt][1];
            rs1 += sc[nt][2] + sc[nt][3];
        }
        rs0 += __shfl_xor_sync(0xffffffffu, rs0, 1);
        rs0 += __shfl_xor_sync(0xffffffffu, rs0, 2);
        rs1 += __shfl_xor_sync(0xffffffffu, rs1, 1);
        rs1 += __shfl_xor_sync(0xffffffffu, rs1, 2);
        l0 = l0 * al0 + rs0;
        l1 = l1 * al1 + rs1;
#pragma unroll
        for (int nt = 0; nt < 8; nt++) {
            ao[nt][0] *= al0; ao[nt][1] *= al0;
            ao[nt][2] *= al1; ao[nt][3] *= al1;
        }

        // stage P (tf32) in per-warp smem rows
        {
            int pr0 = w * 16 + g, pr1 = pr0 + 8;
#pragma unroll
            for (int nt = 0; nt < 8; nt++) {
                int c = nt * 8 + 2 * tg;
                Ps[pr0 * PSS + c]     = tf32r(sc[nt][0]);
                Ps[pr0 * PSS + c + 1] = tf32r(sc[nt][1]);
                Ps[pr1 * PSS + c]     = tf32r(sc[nt][2]);
                Ps[pr1 * PSS + c + 1] = tf32r(sc[nt][3]);
            }
        }
        __syncwarp();

        // O += P V
#pragma unroll
        for (int ks = 0; ks < 8; ks++) {
            const int kb = ks * 8;
            uint32_t pf[4];
            pf[0] = __float_as_uint(Ps[(w * 16 + g) * PSS + kb + tg]);
            pf[1] = __float_as_uint(Ps[(w * 16 + g + 8) * PSS + kb + tg]);
            pf[2] = __float_as_uint(Ps[(w * 16 + g) * PSS + kb + tg + 4]);
            pf[3] = __float_as_uint(Ps[(w * 16 + g + 8) * PSS + kb + tg + 4]);
#pragma unroll
            for (int nt = 0; nt < 8; nt++) {
                uint32_t b0 = __float_as_uint(Vs[(kb + tg) * VSS + nt * 8 + g]);
                uint32_t b1 = __float_as_uint(Vs[(kb + tg + 4) * VSS + nt * 8 + g]);
                mma8(ao[nt], pf, b0, b1);
            }
        }
    }

    // epilogue
    float inv0 = 1.0f / l0, inv1 = 1.0f / l1;
    int r0 = q0 + w * 16 + g, r1 = r0 + 8;
#pragma unroll
    for (int nt = 0; nt < 8; nt++) {
        int c = nt * 8 + 2 * tg;
        *(float2*)&O[(size_t)r0 * DM + h * HD + c] =
            make_float2(ao[nt][0] * inv0, ao[nt][1] * inv0);
        *(float2*)&O[(size_t)r1 * DM + h * HD + c] =
            make_float2(ao[nt][2] * inv1, ao[nt][3] * inv1);
    }
}

// ---------------------------------------------------------------------------
// Launch
// ---------------------------------------------------------------------------
extern "C" void kernel_launch(void* const* d_in, const int* in_sizes, int n_in,
                              void* d_out, int out_size)
{
    (void)in_sizes; (void)n_in; (void)out_size;
    const float* x  = (const float*)d_in[0];
    const float* Wq = (const float*)d_in[2];
    const float* Wk = (const float*)d_in[3];
    const float* Wv = (const float*)d_in[4];
    const float* Wo = (const float*)d_in[5];
    const float* bo = (const float*)d_in[6];
    float* out = (float*)d_out;

    float *Qp, *Kp, *Vp, *AO;
    cudaGetSymbolAddress((void**)&Qp, g_Q);
    cudaGetSymbolAddress((void**)&Kp, g_K);
    cudaGetSymbolAddress((void**)&Vp, g_V);
    cudaGetSymbolAddress((void**)&AO, g_AO);

    cudaFuncSetAttribute(flash_tf32,
                         cudaFuncAttributeMaxDynamicSharedMemorySize, ATT_SMEM);
    cudaFuncSetAttribute(gemm_tf32<false>,
                         cudaFuncAttributeMaxDynamicSharedMemorySize, GEMM_SMEM);
    cudaFuncSetAttribute(gemm_tf32<true>,
                         cudaFuncAttributeMaxDynamicSharedMemorySize, GEMM_SMEM);

    // RoPE tables (must precede QKV gemm epilogue)
    invfreq_kernel<<<1, 32>>>();
    rope_table_kernel<<<(SEQ * 32) / 256, 256>>>();

    // Fused QKV projection + RoPE + tf32 pre-round
    gemm_tf32<false><<<dim3(18, 32), 256, GEMM_SMEM>>>(
        x, Wq, Wk, Wv, nullptr, Qp, Kp, Vp);

    flash_tf32<<<dim3(SEQ / 128, NH), 256, ATT_SMEM>>>(Qp, Kp, Vp, AO);

    // Output projection + bias
    gemm_tf32<true><<<dim3(6, 32), 256, GEMM_SMEM>>>(
        AO, Wo, Wo, Wo, bo, out, out, out);
}